// round 1
// baseline (speedup 1.0000x reference)
#include <cuda_runtime.h>

// Problem constants
#define BB 32
#define SS 8192
#define DD 512
#define MM 16
#define NCHUNK 32
#define ROWS_PER_CHUNK (SS / NCHUNK)       // 256
#define TILE_R 16
#define NTILES (ROWS_PER_CHUNK / TILE_R)   // 16

// Scratch: partial exp-weighted sums per chunk. Fully overwritten every call.
// [chunk][b][m][d]  and  [chunk][b][m]
__device__ float g_acc[(size_t)NCHUNK * BB * MM * DD];   // 33.5 MB
__device__ float g_sum[(size_t)NCHUNK * BB * MM];

using u64 = unsigned long long;

static __device__ __forceinline__ u64 pack2(float lo, float hi) {
    u64 r; asm("mov.b64 %0, {%1, %2};" : "=l"(r) : "f"(lo), "f"(hi)); return r;
}
static __device__ __forceinline__ float2 unpack2(u64 v) {
    float2 f; asm("mov.b64 {%0, %1}, %2;" : "=f"(f.x), "=f"(f.y) : "l"(v)); return f;
}
static __device__ __forceinline__ u64 mul2(u64 a, u64 b) {
    u64 d; asm("mul.rn.f32x2 %0, %1, %2;" : "=l"(d) : "l"(a), "l"(b)); return d;
}
static __device__ __forceinline__ u64 fma2(u64 a, u64 b, u64 c) {
    u64 d; asm("fma.rn.f32x2 %0, %1, %2, %3;" : "=l"(d) : "l"(a), "l"(b), "l"(c)); return d;
}

// ---------------------------------------------------------------------------
// Kernel 1: per (chunk, batch) CTA computes partial sum_s exp(score)*x  and
// partial sum_s exp(score), for all 16 seeds, over 256 rows of x.
//
// 8 warps = 4 seed-groups (4 seeds each) x 2 row-groups (even/odd rows).
// x tile staged in smem; seeds + accumulators register-resident.
// All inner-loop FMAs are packed fma.rn.f32x2 (2x fp32 rate on sm_103a).
// ---------------------------------------------------------------------------
__global__ __launch_bounds__(256, 1)
void ap_pool_partial(const float* __restrict__ x, const float* __restrict__ seeds) {
    __shared__ float s_x[TILE_R * DD];     // 32 KB tile; reused as exchange buf
    __shared__ float s_sum[4][4];

    const int tid  = threadIdx.x;
    const int lane = tid & 31;
    const int warp = tid >> 5;
    const int sg   = warp & 3;    // seed group: seeds [sg*4, sg*4+4)
    const int rg   = warp >> 2;   // row group: rows rg, rg+2, ...
    const int chunk = blockIdx.x;
    const int b     = blockIdx.y;

    const float* xb = x + ((size_t)b * SS + (size_t)chunk * ROWS_PER_CHUNK) * DD;

    // Per-lane dim fragment: d = lane*4 + 128*j + k, j=0..3, k=0..3 (16 dims).
    // Pair index p = 2*j + kk covers dims (lane*4 + 128*j + 2*kk + {0,1}).
    u64 sreg[4][8];
    #pragma unroll
    for (int m = 0; m < 4; m++) {
        #pragma unroll
        for (int j = 0; j < 4; j++) {
            float4 v = *(const float4*)(seeds + (size_t)(sg * 4 + m) * DD + lane * 4 + 128 * j);
            sreg[m][2 * j]     = pack2(v.x, v.y);
            sreg[m][2 * j + 1] = pack2(v.z, v.w);
        }
    }

    u64 acc[4][8];
    #pragma unroll
    for (int m = 0; m < 4; m++)
        #pragma unroll
        for (int p = 0; p < 8; p++)
            acc[m][p] = pack2(0.0f, 0.0f);

    float sum_acc0 = 0.f, sum_acc1 = 0.f, sum_acc2 = 0.f, sum_acc3 = 0.f;

    for (int t = 0; t < NTILES; t++) {
        __syncthreads();
        // Stage tile: 16 rows x 512 fp32 = 2048 float4; 8 per thread, coalesced.
        const float4* src = (const float4*)(xb + (size_t)t * TILE_R * DD);
        float4* dst = (float4*)s_x;
        #pragma unroll
        for (int i = 0; i < 8; i++)
            dst[tid + 256 * i] = src[tid + 256 * i];
        __syncthreads();

        #pragma unroll 2
        for (int rr = 0; rr < TILE_R / 2; rr++) {
            const int r = rr * 2 + rg;
            const float* row = s_x + r * DD + lane * 4;

            u64 xv[8];
            #pragma unroll
            for (int j = 0; j < 4; j++) {
                float4 v = *(const float4*)(row + 128 * j);
                xv[2 * j]     = pack2(v.x, v.y);
                xv[2 * j + 1] = pack2(v.z, v.w);
            }

            // scores: 4 packed dot-partials
            u64 p2[4];
            #pragma unroll
            for (int m = 0; m < 4; m++) {
                u64 acc2 = mul2(xv[0], sreg[m][0]);
                #pragma unroll
                for (int p = 1; p < 8; p++)
                    acc2 = fma2(xv[p], sreg[m][p], acc2);
                p2[m] = acc2;
            }

            float pm[4];
            #pragma unroll
            for (int m = 0; m < 4; m++) {
                float2 f = unpack2(p2[m]);
                pm[m] = f.x + f.y;
            }
            // butterfly reduce across 32 lanes (all 4 chains independent)
            #pragma unroll
            for (int off = 16; off > 0; off >>= 1) {
                #pragma unroll
                for (int m = 0; m < 4; m++)
                    pm[m] += __shfl_xor_sync(0xffffffffu, pm[m], off);
            }

            // scores are bounded (|score| < ~10): exp without max-shift is safe
            float e0 = __expf(pm[0]);
            float e1 = __expf(pm[1]);
            float e2 = __expf(pm[2]);
            float e3 = __expf(pm[3]);
            sum_acc0 += e0; sum_acc1 += e1; sum_acc2 += e2; sum_acc3 += e3;

            u64 eb[4];
            eb[0] = pack2(e0, e0); eb[1] = pack2(e1, e1);
            eb[2] = pack2(e2, e2); eb[3] = pack2(e3, e3);

            #pragma unroll
            for (int m = 0; m < 4; m++) {
                #pragma unroll
                for (int p = 0; p < 8; p++)
                    acc[m][p] = fma2(eb[m], xv[p], acc[m][p]);
            }
        }
    }

    // --- Epilogue: combine the two row-groups, write partials to scratch ---
    __syncthreads();   // tile buffer free now; reuse as exchange (exactly 8192 floats)
    if (rg == 1) {
        #pragma unroll
        for (int m = 0; m < 4; m++) {
            #pragma unroll
            for (int j = 0; j < 4; j++) {
                float2 a = unpack2(acc[m][2 * j]);
                float2 c = unpack2(acc[m][2 * j + 1]);
                float4 v = make_float4(a.x, a.y, c.x, c.y);
                *(float4*)(s_x + (size_t)(sg * 4 + m) * DD + lane * 4 + 128 * j) = v;
            }
        }
        if (lane == 0) {
            s_sum[sg][0] = sum_acc0; s_sum[sg][1] = sum_acc1;
            s_sum[sg][2] = sum_acc2; s_sum[sg][3] = sum_acc3;
        }
    }
    __syncthreads();
    if (rg == 0) {
        float* gbase = g_acc + ((size_t)(chunk * BB + b) * MM + sg * 4) * DD;
        #pragma unroll
        for (int m = 0; m < 4; m++) {
            #pragma unroll
            for (int j = 0; j < 4; j++) {
                float2 a = unpack2(acc[m][2 * j]);
                float2 c = unpack2(acc[m][2 * j + 1]);
                float4 o = *(const float4*)(s_x + (size_t)(sg * 4 + m) * DD + lane * 4 + 128 * j);
                o.x += a.x; o.y += a.y; o.z += c.x; o.w += c.y;
                *(float4*)(gbase + (size_t)m * DD + lane * 4 + 128 * j) = o;
            }
        }
        if (lane == 0) {
            float* gs = g_sum + (size_t)(chunk * BB + b) * MM + sg * 4;
            gs[0] = sum_acc0 + s_sum[sg][0];
            gs[1] = sum_acc1 + s_sum[sg][1];
            gs[2] = sum_acc2 + s_sum[sg][2];
            gs[3] = sum_acc3 + s_sum[sg][3];
        }
    }
}

// ---------------------------------------------------------------------------
// Kernel 2: combine NCHUNK partials and normalize.
// out[b][m][d] = sum_c g_acc[c][bm][d] / sum_c g_sum[c][bm]
// ---------------------------------------------------------------------------
__global__ __launch_bounds__(128)
void ap_pool_combine(float* __restrict__ out) {
    const int bm  = blockIdx.x;       // 0 .. B*M-1
    const int tid = threadIdx.x;      // 128 threads; 4 dims each

    float s = 0.f;
    #pragma unroll
    for (int c = 0; c < NCHUNK; c++)
        s += g_sum[(size_t)c * BB * MM + bm];
    const float inv = 1.0f / s;

    float4 a = make_float4(0.f, 0.f, 0.f, 0.f);
    #pragma unroll
    for (int c = 0; c < NCHUNK; c++) {
        float4 v = *(const float4*)(g_acc + ((size_t)c * BB * MM + bm) * DD + tid * 4);
        a.x += v.x; a.y += v.y; a.z += v.z; a.w += v.w;
    }
    a.x *= inv; a.y *= inv; a.z *= inv; a.w *= inv;
    *(float4*)(out + (size_t)bm * DD + tid * 4) = a;
}

extern "C" void kernel_launch(void* const* d_in, const int* in_sizes, int n_in,
                              void* d_out, int out_size) {
    const float* x     = (const float*)d_in[0];   // [32, 8192, 512] f32
    const float* seeds = (const float*)d_in[1];   // [16, 512] f32
    float* out = (float*)d_out;                   // [32, 16, 512] f32

    dim3 grid(NCHUNK, BB);
    ap_pool_partial<<<grid, 256>>>(x, seeds);
    ap_pool_combine<<<BB * MM, 128>>>(out);
}

// round 3
// speedup vs baseline: 1.0008x; 1.0008x over previous
#include <cuda_runtime.h>

// Problem constants
#define BB 32
#define SS 8192
#define DD 512
#define MM 16
#define NCHUNK 32
#define ROWS_PER_CHUNK (SS / NCHUNK)       // 256
#define TILE_R 16
#define NTILES (ROWS_PER_CHUNK / TILE_R)   // 16

// Scratch: partial exp-weighted sums per chunk. Fully overwritten every call.
// [chunk][b][m][d]  and  [chunk][b][m]
__device__ float g_acc[(size_t)NCHUNK * BB * MM * DD];   // 33.5 MB
__device__ float g_sum[(size_t)NCHUNK * BB * MM];

using u64 = unsigned long long;

static __device__ __forceinline__ u64 pack2(float lo, float hi) {
    u64 r; asm("mov.b64 %0, {%1, %2};" : "=l"(r) : "f"(lo), "f"(hi)); return r;
}
static __device__ __forceinline__ float2 unpack2(u64 v) {
    float2 f; asm("mov.b64 {%0, %1}, %2;" : "=f"(f.x), "=f"(f.y) : "l"(v)); return f;
}
static __device__ __forceinline__ u64 mul2(u64 a, u64 b) {
    u64 d; asm("mul.rn.f32x2 %0, %1, %2;" : "=l"(d) : "l"(a), "l"(b)); return d;
}
static __device__ __forceinline__ u64 fma2(u64 a, u64 b, u64 c) {
    u64 d; asm("fma.rn.f32x2 %0, %1, %2, %3;" : "=l"(d) : "l"(a), "l"(b), "l"(c)); return d;
}

// ---------------------------------------------------------------------------
// Kernel 1: per (chunk, batch) CTA computes partial sum_s exp(score)*x  and
// partial sum_s exp(score), for all 16 seeds, over 256 rows of x.
//
// 8 warps = 4 seed-groups (4 seeds each) x 2 row-groups (even/odd rows).
// x tile staged in smem; seeds + accumulators register-resident.
// All inner-loop FMAs are packed fma.rn.f32x2 (2x fp32 rate on sm_103a).
// ---------------------------------------------------------------------------
__global__ __launch_bounds__(256, 1)
void ap_pool_partial(const float* __restrict__ x, const float* __restrict__ seeds) {
    __shared__ float s_x[TILE_R * DD];     // 32 KB tile; reused as exchange buf
    __shared__ float s_sum[4][4];

    const int tid  = threadIdx.x;
    const int lane = tid & 31;
    const int warp = tid >> 5;
    const int sg   = warp & 3;    // seed group: seeds [sg*4, sg*4+4)
    const int rg   = warp >> 2;   // row group: rows rg, rg+2, ...
    const int chunk = blockIdx.x;
    const int b     = blockIdx.y;

    const float* xb = x + ((size_t)b * SS + (size_t)chunk * ROWS_PER_CHUNK) * DD;

    // Per-lane dim fragment: d = lane*4 + 128*j + k, j=0..3, k=0..3 (16 dims).
    // Pair index p = 2*j + kk covers dims (lane*4 + 128*j + 2*kk + {0,1}).
    u64 sreg[4][8];
    #pragma unroll
    for (int m = 0; m < 4; m++) {
        #pragma unroll
        for (int j = 0; j < 4; j++) {
            float4 v = *(const float4*)(seeds + (size_t)(sg * 4 + m) * DD + lane * 4 + 128 * j);
            sreg[m][2 * j]     = pack2(v.x, v.y);
            sreg[m][2 * j + 1] = pack2(v.z, v.w);
        }
    }

    u64 acc[4][8];
    #pragma unroll
    for (int m = 0; m < 4; m++)
        #pragma unroll
        for (int p = 0; p < 8; p++)
            acc[m][p] = pack2(0.0f, 0.0f);

    float sum_acc0 = 0.f, sum_acc1 = 0.f, sum_acc2 = 0.f, sum_acc3 = 0.f;

    for (int t = 0; t < NTILES; t++) {
        __syncthreads();
        // Stage tile: 16 rows x 512 fp32 = 2048 float4; 8 per thread, coalesced.
        const float4* src = (const float4*)(xb + (size_t)t * TILE_R * DD);
        float4* dst = (float4*)s_x;
        #pragma unroll
        for (int i = 0; i < 8; i++)
            dst[tid + 256 * i] = src[tid + 256 * i];
        __syncthreads();

        #pragma unroll 2
        for (int rr = 0; rr < TILE_R / 2; rr++) {
            const int r = rr * 2 + rg;
            const float* row = s_x + r * DD + lane * 4;

            u64 xv[8];
            #pragma unroll
            for (int j = 0; j < 4; j++) {
                float4 v = *(const float4*)(row + 128 * j);
                xv[2 * j]     = pack2(v.x, v.y);
                xv[2 * j + 1] = pack2(v.z, v.w);
            }

            // scores: 4 packed dot-partials
            u64 p2[4];
            #pragma unroll
            for (int m = 0; m < 4; m++) {
                u64 acc2 = mul2(xv[0], sreg[m][0]);
                #pragma unroll
                for (int p = 1; p < 8; p++)
                    acc2 = fma2(xv[p], sreg[m][p], acc2);
                p2[m] = acc2;
            }

            float pm[4];
            #pragma unroll
            for (int m = 0; m < 4; m++) {
                float2 f = unpack2(p2[m]);
                pm[m] = f.x + f.y;
            }
            // butterfly reduce across 32 lanes (all 4 chains independent)
            #pragma unroll
            for (int off = 16; off > 0; off >>= 1) {
                #pragma unroll
                for (int m = 0; m < 4; m++)
                    pm[m] += __shfl_xor_sync(0xffffffffu, pm[m], off);
            }

            // scores are bounded (|score| < ~10): exp without max-shift is safe
            float e0 = __expf(pm[0]);
            float e1 = __expf(pm[1]);
            float e2 = __expf(pm[2]);
            float e3 = __expf(pm[3]);
            sum_acc0 += e0; sum_acc1 += e1; sum_acc2 += e2; sum_acc3 += e3;

            u64 eb[4];
            eb[0] = pack2(e0, e0); eb[1] = pack2(e1, e1);
            eb[2] = pack2(e2, e2); eb[3] = pack2(e3, e3);

            #pragma unroll
            for (int m = 0; m < 4; m++) {
                #pragma unroll
                for (int p = 0; p < 8; p++)
                    acc[m][p] = fma2(eb[m], xv[p], acc[m][p]);
            }
        }
    }

    // --- Epilogue: combine the two row-groups, write partials to scratch ---
    __syncthreads();   // tile buffer free now; reuse as exchange (exactly 8192 floats)
    if (rg == 1) {
        #pragma unroll
        for (int m = 0; m < 4; m++) {
            #pragma unroll
            for (int j = 0; j < 4; j++) {
                float2 a = unpack2(acc[m][2 * j]);
                float2 c = unpack2(acc[m][2 * j + 1]);
                float4 v = make_float4(a.x, a.y, c.x, c.y);
                *(float4*)(s_x + (size_t)(sg * 4 + m) * DD + lane * 4 + 128 * j) = v;
            }
        }
        if (lane == 0) {
            s_sum[sg][0] = sum_acc0; s_sum[sg][1] = sum_acc1;
            s_sum[sg][2] = sum_acc2; s_sum[sg][3] = sum_acc3;
        }
    }
    __syncthreads();
    if (rg == 0) {
        float* gbase = g_acc + ((size_t)(chunk * BB + b) * MM + sg * 4) * DD;
        #pragma unroll
        for (int m = 0; m < 4; m++) {
            #pragma unroll
            for (int j = 0; j < 4; j++) {
                float2 a = unpack2(acc[m][2 * j]);
                float2 c = unpack2(acc[m][2 * j + 1]);
                float4 o = *(const float4*)(s_x + (size_t)(sg * 4 + m) * DD + lane * 4 + 128 * j);
                o.x += a.x; o.y += a.y; o.z += c.x; o.w += c.y;
                *(float4*)(gbase + (size_t)m * DD + lane * 4 + 128 * j) = o;
            }
        }
        if (lane == 0) {
            float* gs = g_sum + (size_t)(chunk * BB + b) * MM + sg * 4;
            gs[0] = sum_acc0 + s_sum[sg][0];
            gs[1] = sum_acc1 + s_sum[sg][1];
            gs[2] = sum_acc2 + s_sum[sg][2];
            gs[3] = sum_acc3 + s_sum[sg][3];
        }
    }
}

// ---------------------------------------------------------------------------
// Kernel 2: combine NCHUNK partials and normalize.
// out[b][m][d] = sum_c g_acc[c][bm][d] / sum_c g_sum[c][bm]
// ---------------------------------------------------------------------------
__global__ __launch_bounds__(128)
void ap_pool_combine(float* __restrict__ out) {
    const int bm  = blockIdx.x;       // 0 .. B*M-1
    const int tid = threadIdx.x;      // 128 threads; 4 dims each

    float s = 0.f;
    #pragma unroll
    for (int c = 0; c < NCHUNK; c++)
        s += g_sum[(size_t)c * BB * MM + bm];
    const float inv = 1.0f / s;

    float4 a = make_float4(0.f, 0.f, 0.f, 0.f);
    #pragma unroll
    for (int c = 0; c < NCHUNK; c++) {
        float4 v = *(const float4*)(g_acc + ((size_t)c * BB * MM + bm) * DD + tid * 4);
        a.x += v.x; a.y += v.y; a.z += v.z; a.w += v.w;
    }
    a.x *= inv; a.y *= inv; a.z *= inv; a.w *= inv;
    *(float4*)(out + (size_t)bm * DD + tid * 4) = a;
}

extern "C" void kernel_launch(void* const* d_in, const int* in_sizes, int n_in,
                              void* d_out, int out_size) {
    const float* x     = (const float*)d_in[0];   // [32, 8192, 512] f32
    const float* seeds = (const float*)d_in[1];   // [16, 512] f32
    float* out = (float*)d_out;                   // [32, 16, 512] f32

    dim3 grid(NCHUNK, BB);
    ap_pool_partial<<<grid, 256>>>(x, seeds);
    ap_pool_combine<<<BB * MM, 128>>>(out);
}